// round 16
// baseline (speedup 1.0000x reference)
#include <cuda_runtime.h>
#include <cuda_fp16.h>
#include <math.h>
#include <stdint.h>

#define NN 100000
#define NN2 100032          // padded to multiple of 64
#define NE 3200000
#define NT64 1563           // ceil(NN / 64)

typedef unsigned long long ull;

// ---------------- device scratch ----------------
__device__ float g_a[NN2 * 12];        // segment sums, padded stride 12
__device__ float g_xp[NN * 12];        // [x0..x7][x8, py, pz, px]
__device__ __half g_outTh[480 * (size_t)NN2];  // fp16 transposed staging [feat][node]
__device__ float g_C112[45];
__device__ float g_W222[125];
__device__ __align__(16) float g_scale[480];
__device__ __align__(16) float g_bias[480];

__device__ __forceinline__ float fsigmoid(float x) {
    return __fdividef(1.f, 1.f + __expf(-x));
}
__device__ __forceinline__ ull pack2(float a, float b) {
    ull r; asm("mov.b64 %0, {%1,%2};" : "=l"(r) : "f"(a), "f"(b)); return r;
}
__device__ __forceinline__ void fma2(ull& d, ull a, ull b) {
    asm("fma.rn.f32x2 %0, %1, %2, %0;" : "+l"(d) : "l"(a), "l"(b));
}
__device__ __forceinline__ void unpack2(ull v, float& a, float& b) {
    asm("mov.b64 {%0,%1}, %2;" : "=f"(a), "=f"(b) : "l"(v));
}
__device__ __forceinline__ void st_h2_cs(__half* p, float a, float b) {
    __half2 h = __floats2half2_rn(a, b);
    unsigned int bits = *(unsigned int*)&h;
    asm volatile("st.global.cs.b32 [%0], %1;" :: "l"(p), "r"(bits) : "memory");
}

// ---------------- prep: pad x + pos fused, zero scratch, constants (block 0) ----------------
__global__ void k_prep(const float* __restrict__ x, const float* __restrict__ pos) {
    int n = blockIdx.x * blockDim.x + threadIdx.x;
    if (n < NN2) {
        float4 z = make_float4(0.f, 0.f, 0.f, 0.f);
        float4* ga = (float4*)(g_a + 12 * (size_t)n);
        ga[0] = z; ga[1] = z; ga[2] = z;
    }
    if (n < NN) {
        const float* xs = x + 9 * (size_t)n;
        float4* xp = (float4*)(g_xp + 12 * (size_t)n);
        xp[0] = make_float4(xs[0], xs[1], xs[2], xs[3]);
        xp[1] = make_float4(xs[4], xs[5], xs[6], xs[7]);
        xp[2] = make_float4(xs[8], pos[3 * n + 1], pos[3 * n + 2], pos[3 * n + 0]);
    }

    if (blockIdx.x == 0) {
        __shared__ float A[48];
        __shared__ float Ws[125];
        const int t = threadIdx.x;
        if (t < 45) A[t] = 0.f;
        __syncthreads();
        if (t == 0) {
            const float h = sqrtf(15.f) * 0.5f;
            const float s5 = sqrtf(5.f);
            A[0 * 9 + 0 * 3 + 2] = h; A[0 * 9 + 2 * 3 + 0] = h;
            A[1 * 9 + 0 * 3 + 1] = h; A[1 * 9 + 1 * 3 + 0] = h;
            A[2 * 9 + 0 * 3 + 0] = -0.5f * s5; A[2 * 9 + 1 * 3 + 1] = s5; A[2 * 9 + 2 * 3 + 2] = -0.5f * s5;
            A[3 * 9 + 1 * 3 + 2] = h; A[3 * 9 + 2 * 3 + 1] = h;
            A[4 * 9 + 0 * 3 + 0] = -h; A[4 * 9 + 2 * 3 + 2] = h;
        }
        __syncthreads();
        float ss = 0.f;
        for (int i = 0; i < 45; i++) ss += A[i] * A[i];
        float inv = 1.f / sqrtf(ss);
        if (t < 45) {
            int i = t / 15, j = (t % 15) / 5, m = t % 5;
            g_C112[t] = A[m * 9 + i * 3 + j] * inv;
        }
        if (t < 125) {
            int m = t / 25, nn = (t / 5) % 5, p = t % 5;
            float acc = 0.f, acc2 = 0.f;
            for (int i = 0; i < 3; i++)
                for (int k = 0; k < 3; k++)
                    for (int j = 0; j < 3; j++) {
                        acc  += A[m * 9 + i * 3 + k] * A[nn * 9 + k * 3 + j] * A[p * 9 + j * 3 + i];
                        acc2 += A[nn * 9 + i * 3 + k] * A[m * 9 + k * 3 + j] * A[p * 9 + j * 3 + i];
                    }
            Ws[t] = acc + acc2;
        }
        __syncthreads();
        if (t < 125) {
            float ss2 = 0.f;
            for (int i = 0; i < 125; i++) ss2 += Ws[i] * Ws[i];
            g_W222[t] = Ws[t] * (1.f / sqrtf(ss2));
        }
    }
}

// ---------------- edge kernel ----------------
__global__ void __launch_bounds__(256) k_edge(
    const int* __restrict__ ei,
    float* __restrict__ erbf, float* __restrict__ ersh)
{
    __shared__ float s_rbf[16 * 257];                 // [comp][edge], column-major
    __shared__ __align__(16) float s_sh9[256 * 9];    // [edge][comp], packed
    const int tid = threadIdx.x;
    const int e0 = blockIdx.x * 256;
    const int e = e0 + tid;

    int s = ei[e];
    int t = ei[NE + e];
    const float4* xps = (const float4*)(g_xp + 12 * (size_t)s);
    float4 xs2 = xps[2];
    float4 xt2 = ((const float4*)(g_xp + 12 * (size_t)t))[2];
    float vx = xt2.y - xs2.y, vy = xt2.z - xs2.z, vz = xt2.w - xs2.w;
    float r2 = vx * vx + vy * vy + vz * vz;
    float r = sqrtf(r2);
    float inv = __fdividef(1.f, fmaxf(r, 1e-12f));
    float ux = vx * inv, uy = vy * inv, uz = vz * inv;
    const float SQ3 = 1.7320508075688772f;
    const float SQ5 = 2.2360679774997896f;
    const float SQ15 = 3.8729833462074170f;
    float sh1 = SQ3 * ux, sh2 = SQ3 * uy, sh3 = SQ3 * uz;
    float sh4 = SQ15 * ux * uz;
    float sh5 = SQ15 * ux * uy;
    float sh6 = SQ5 * (uy * uy - 0.5f * (ux * ux + uz * uz));
    float sh7 = SQ15 * uy * uz;
    float sh8 = 0.5f * SQ15 * (uz * uz - ux * ux);
    float d = r * 0.1f;
    float d2 = d * d;
    float d5 = d2 * d2 * d;
    float fc = 1.f + d5 * (-21.f + d * (35.f - 15.f * d));
    fc = (d < 1.f) ? fc : 0.f;
    float ee = __expf(-d2) * fc;
    float g0 = ee, g1 = d * ee, g2 = d2 * ee;

    float4 xa = xps[0], xb = xps[1];
    float x8 = xs2.x;

    float* ga = g_a + 12 * (size_t)t;
    float m0 = xa.x * g0;
    float m1 = xa.y * sh1 * g1;
    float m2 = xa.z * sh2 * g1;
    float m3 = xa.w * sh3 * g1;
    float m4 = xb.x * sh4 * g2;
    float m5 = xb.y * sh5 * g2;
    float m6 = xb.z * sh6 * g2;
    float m7 = xb.w * sh7 * g2;
    float m8 = x8   * sh8 * g2;
    asm volatile("red.global.add.v4.f32 [%0], {%1,%2,%3,%4};"
                 :: "l"(ga), "f"(m0), "f"(m1), "f"(m2), "f"(m3) : "memory");
    asm volatile("red.global.add.v4.f32 [%0], {%1,%2,%3,%4};"
                 :: "l"(ga + 4), "f"(m4), "f"(m5), "f"(m6), "f"(m7) : "memory");
    atomicAdd(ga + 8, m8);

    float sp, cp;
    __sincosf(0.31415926535897931f * r, &sp, &cp);
    float coef = 0.44721359549995793f * inv * fc;
    float sprev = 0.f, scur = sp;
    float twoc = 2.f * cp;
#pragma unroll
    for (int n = 0; n < 16; n++) {
        s_rbf[n * 257 + tid] = coef * scur;
        float nx = twoc * scur - sprev;
        sprev = scur; scur = nx;
    }
    float* es = s_sh9 + tid * 9;
    es[0] = 1.f;
    es[1] = -sh1; es[2] = -sh2; es[3] = -sh3;
    es[4] = sh4; es[5] = sh5; es[6] = sh6; es[7] = sh7; es[8] = sh8;
    __syncthreads();

    float4* eb4 = (float4*)(erbf + (size_t)e0 * 16);
#pragma unroll
    for (int i = 0; i < 4; i++) {
        int k = tid + 256 * i;
        int eg = k >> 2, c0 = (k & 3) * 4;
        float4 v = make_float4(s_rbf[(c0 + 0) * 257 + eg], s_rbf[(c0 + 1) * 257 + eg],
                               s_rbf[(c0 + 2) * 257 + eg], s_rbf[(c0 + 3) * 257 + eg]);
        __stcs(&eb4[k], v);
    }
    float4* ep4 = (float4*)(ersh + (size_t)e0 * 9);
    const float4* ss4 = (const float4*)s_sh9;
    __stcs(&ep4[tid], ss4[tid]);
    __stcs(&ep4[tid + 256], ss4[tid + 256]);
    if (tid < 64) __stcs(&ep4[tid + 512], ss4[tid + 512]);
}

// ---------------- node kernel ----------------
#define SM_W0A   0        // 384
#define SM_W1A   384      // 256
#define SM_W2A   640      // 128
#define SM_W0B   768      // 16384 [k][f]
#define SM_W1B   17152    // 4096  [u][v]
#define SM_W2B   21248    // 1024  [u][v]
#define SM_TPW   22272    // 12
#define SM_C112  22284    // 48
#define SM_W222  22332    // 128
#define SM_S     22460    // 64*13 = 832
#define SM_OUTT  23292    // 35*64 = 2240
#define SM_H0    25532    // 128*64 = 8192
#define SM_H1    33724    // 192*64 = 12288
#define SM_H2    46012    // 160*64 = 10240
#define SMEM_FLOATS 56252
#define SMEM_BYTES (SMEM_FLOATS * 4)

template<int K, int WS, int AS>
__device__ __forceinline__ void taskB64(const float* __restrict__ ap,
                                        const ulonglong2* __restrict__ wp,
                                        __half* __restrict__ op, size_t rstride)
{
    ull A[8], B[8];
#pragma unroll
    for (int j = 0; j < 8; j++) { A[j] = 0; B[j] = 0; }
#pragma unroll 8
    for (int u = 0; u < K; u++) {
        ull av = *(const ull*)(ap + u * AS);
        float a0, a1; unpack2(av, a0, a1);
        ull p0 = pack2(a0, a0), p1 = pack2(a1, a1);
        ulonglong2 q0 = wp[u * WS],     q1 = wp[u * WS + 1];
        ulonglong2 q2 = wp[u * WS + 2], q3 = wp[u * WS + 3];
        fma2(A[0], p0, q0.x); fma2(B[0], p1, q0.x);
        fma2(A[1], p0, q0.y); fma2(B[1], p1, q0.y);
        fma2(A[2], p0, q1.x); fma2(B[2], p1, q1.x);
        fma2(A[3], p0, q1.y); fma2(B[3], p1, q1.y);
        fma2(A[4], p0, q2.x); fma2(B[4], p1, q2.x);
        fma2(A[5], p0, q2.y); fma2(B[5], p1, q2.y);
        fma2(A[6], p0, q3.x); fma2(B[6], p1, q3.x);
        fma2(A[7], p0, q3.y); fma2(B[7], p1, q3.y);
    }
#pragma unroll
    for (int j = 0; j < 8; j++) {
        float a0, a1, b0, b1;
        unpack2(A[j], a0, a1);
        unpack2(B[j], b0, b1);
        st_h2_cs(op + (size_t)(2 * j) * rstride,     a0, b0);
        st_h2_cs(op + (size_t)(2 * j + 1) * rstride, a1, b1);
    }
}

__global__ void __launch_bounds__(512) k_node(
    const float* __restrict__ tp_w,
    const float* __restrict__ W0a, const float* __restrict__ W1a, const float* __restrict__ W2a,
    const float* __restrict__ W0b, const float* __restrict__ W1b, const float* __restrict__ W2b)
{
    extern __shared__ float sm[];
    float* w0a  = sm + SM_W0A;
    float* w1a  = sm + SM_W1A;
    float* w2a  = sm + SM_W2A;
    float* w0b  = sm + SM_W0B;
    float* w1b  = sm + SM_W1B;
    float* w2b  = sm + SM_W2B;
    float* tpw  = sm + SM_TPW;
    float* c112 = sm + SM_C112;
    float* w222 = sm + SM_W222;
    float* s_sh = sm + SM_S;
    float* out_t = sm + SM_OUTT;
    float* h0aT = sm + SM_H0;
    float* h1aT = sm + SM_H1;
    float* h2aT = sm + SM_H2;

    const int tid = threadIdx.x;
    const int wid = tid >> 5;
    const int lane = tid & 31;

    for (int i = tid; i < 384; i += 512) w0a[i] = W0a[i];
    if (tid < 256) w1a[tid] = W1a[tid];
    if (tid >= 256 && tid < 384) w2a[tid - 256] = W2a[tid - 256];
    for (int i = tid; i < 16384; i += 512) w0b[i] = W0b[i];
    for (int i = tid; i < 4096;  i += 512) w1b[i] = W1b[i];
    for (int i = tid; i < 1024;  i += 512) w2b[i] = W2b[i];
    if (tid < 11)  tpw[tid]  = tp_w[tid];
    if (tid >= 32 && tid < 77)  c112[tid - 32] = g_C112[tid - 32];
    if (tid >= 128 && tid < 253) w222[tid - 128] = g_W222[tid - 128];
    __syncthreads();

    for (int tile = blockIdx.x; tile < NT64; tile += gridDim.x) {
        const int n0 = tile * 64;

        if (tid < 192) {
            int n = tid / 3;
            int c = tid - 3 * n;
            const float4* gp = (const float4*)(g_a + (size_t)(n0 + n) * 12);
            float4 v = gp[c];
            float* dst = s_sh + n * 13 + c * 4;
            dst[0] = v.x; dst[1] = v.y; dst[2] = v.z; dst[3] = v.w;
        }
        __syncthreads();

#pragma unroll
        for (int half = 0; half < 2; half++) {
            const int node = half * 32 + lane;
            float s[9];
#pragma unroll
            for (int i = 0; i < 9; i++) s[i] = s_sh[node * 13 + i];
#pragma unroll
            for (int kq = 0; kq < 3; kq++) {
                int q = wid + 16 * kq;
                if (q >= 35) continue;
                float val;
                if (q == 0) {
                    val = tpw[0] * s[0] * s[0];
                } else if (q == 1) {
                    float a = s[1] * s[1] + s[2] * s[2] + s[3] * s[3];
                    val = tpw[1] * a * 0.57735026918962573f;
                } else if (q == 2) {
                    float a = 0.f;
#pragma unroll
                    for (int m = 0; m < 5; m++) a = fmaf(s[4 + m], s[4 + m], a);
                    val = tpw[2] * a * 0.44721359549995793f;
                } else if (q < 6) {
                    val = tpw[3] * s[0] * s[1 + (q - 3)];
                } else if (q < 9) {
                    val = tpw[4] * s[1 + (q - 6)] * s[0];
                } else if (q < 12) {
                    int j = q - 9; float a = 0.f;
#pragma unroll
                    for (int i = 0; i < 3; i++)
#pragma unroll
                        for (int m = 0; m < 5; m++)
                            a = fmaf(c112[i * 15 + j * 5 + m], s[1 + i] * s[4 + m], a);
                    val = tpw[5] * a;
                } else if (q < 15) {
                    int i = q - 12; float a = 0.f;
#pragma unroll
                    for (int j = 0; j < 3; j++)
#pragma unroll
                        for (int m = 0; m < 5; m++)
                            a = fmaf(c112[i * 15 + j * 5 + m], s[1 + j] * s[4 + m], a);
                    val = tpw[6] * a;
                } else if (q < 20) {
                    val = tpw[7] * s[0] * s[4 + (q - 15)];
                } else if (q < 25) {
                    val = tpw[8] * s[4 + (q - 20)] * s[0];
                } else if (q < 30) {
                    int m = q - 25; float a = 0.f;
#pragma unroll
                    for (int i = 0; i < 3; i++)
#pragma unroll
                        for (int j = 0; j < 3; j++)
                            a = fmaf(c112[i * 15 + j * 5 + m], s[1 + i] * s[1 + j], a);
                    val = tpw[9] * a;
                } else {
                    int c = q - 30; float a = 0.f;
#pragma unroll
                    for (int aa = 0; aa < 5; aa++)
#pragma unroll
                        for (int bb = 0; bb < 5; bb++)
                            a = fmaf(w222[(aa * 5 + bb) * 5 + c], s[4 + aa] * s[4 + bb], a);
                    val = tpw[10] * a;
                }
                out_t[q * 64 + node] = val;
            }
        }
        __syncthreads();

#pragma unroll
        for (int half = 0; half < 2; half++) {
            const int node = half * 32 + lane;
            float o0 = out_t[node], o1 = out_t[64 + node], o2 = out_t[128 + node];
#pragma unroll
            for (int k = 0; k < 8; k++) {
                int f = wid + 16 * k;
                float hv = o0 * w0a[f] + o1 * w0a[128 + f] + o2 * w0a[256 + f];
                h0aT[f * 64 + node] = fsigmoid(hv);
            }
            float b1[12];
#pragma unroll
            for (int i = 0; i < 12; i++) b1[i] = out_t[(3 + i) * 64 + node];
#pragma unroll
            for (int k = 0; k < 4; k++) {
                int v = wid + 16 * k;
                float m0 = 0.f, m1 = 0.f, m2 = 0.f;
#pragma unroll
                for (int u = 0; u < 4; u++) {
                    float w = w1a[u * 64 + v];
                    m0 = fmaf(b1[u * 3 + 0], w, m0);
                    m1 = fmaf(b1[u * 3 + 1], w, m1);
                    m2 = fmaf(b1[u * 3 + 2], w, m2);
                }
                float gt = fsigmoid(sqrtf(m0 * m0 + m1 * m1 + m2 * m2));
                h1aT[(v * 3 + 0) * 64 + node] = m0 * gt;
                h1aT[(v * 3 + 1) * 64 + node] = m1 * gt;
                h1aT[(v * 3 + 2) * 64 + node] = m2 * gt;
            }
            float b2[20];
#pragma unroll
            for (int i = 0; i < 20; i++) b2[i] = out_t[(15 + i) * 64 + node];
#pragma unroll
            for (int k = 0; k < 2; k++) {
                int v = wid + 16 * k;
                float m[5] = {0.f, 0.f, 0.f, 0.f, 0.f};
#pragma unroll
                for (int u = 0; u < 4; u++) {
                    float w = w2a[u * 32 + v];
#pragma unroll
                    for (int mm = 0; mm < 5; mm++)
                        m[mm] = fmaf(b2[u * 5 + mm], w, m[mm]);
                }
                float nrm = m[0]*m[0] + m[1]*m[1] + m[2]*m[2] + m[3]*m[3] + m[4]*m[4];
                float gt = fsigmoid(sqrtf(nrm));
#pragma unroll
                for (int mm = 0; mm < 5; mm++) h2aT[(v * 5 + mm) * 64 + node] = m[mm] * gt;
            }
        }
        __syncthreads();

#pragma unroll
        for (int k8 = 0; k8 < 2; k8++) {
            const int t = wid + 16 * k8;
            if (t >= 30) continue;
            if (t < 8) {
                taskB64<128, 32, 64>(h0aT + 2 * lane,
                                     (const ulonglong2*)w0b + 4 * t,
                                     g_outTh + (size_t)(16 * t) * NN2 + n0 + 2 * lane,
                                     (size_t)NN2);
            } else if (t < 20) {
                const int idx = t - 8, m = idx >> 2, vg = idx & 3;
                taskB64<64, 16, 192>(h1aT + m * 64 + 2 * lane,
                                     (const ulonglong2*)w1b + 4 * vg,
                                     g_outTh + (size_t)(128 + 48 * vg + m) * NN2 + n0 + 2 * lane,
                                     (size_t)(3 * NN2));
            } else {
                const int idx = t - 20, m = idx >> 1, vg = idx & 1;
                taskB64<32, 8, 320>(h2aT + m * 64 + 2 * lane,
                                    (const ulonglong2*)w2b + 4 * vg,
                                    g_outTh + (size_t)(320 + 80 * vg + m) * NN2 + n0 + 2 * lane,
                                    (size_t)(5 * NN2));
            }
        }
        __syncthreads();
    }
}

// ---------------- fused stats + scale (224 blocks aligned to norm groups) ----------------
// block b < 128: h0 feature b (1 row, mean/var)
// block 128+v (v<64): h1 group v (3 rows, rms)
// block 192+v (v<32): h2 group v (5 rows, rms)
__global__ void __launch_bounds__(512) k_stats() {
    const int b = blockIdx.x;
    const float EPS = 1e-5f;
    const float invN = 1.f / (float)NN;
    int row0, nrows;
    if (b < 128)      { row0 = b;                  nrows = 1; }
    else if (b < 192) { row0 = 128 + 3 * (b - 128); nrows = 3; }
    else              { row0 = 320 + 5 * (b - 192); nrows = 5; }

    const int R = NN / 8;        // 12500 uint4 per row
    float s = 0.f, q = 0.f;
    for (int i = threadIdx.x; i < nrows * R; i += 512) {
        int rr = i / R, idx = i - rr * R;
        const uint4* row = (const uint4*)(g_outTh + (size_t)(row0 + rr) * NN2);
        uint4 raw = __ldcs(row + idx);
        float2 a = __half22float2(*(__half2*)&raw.x);
        float2 bb = __half22float2(*(__half2*)&raw.y);
        float2 c = __half22float2(*(__half2*)&raw.z);
        float2 d = __half22float2(*(__half2*)&raw.w);
        s += (a.x + a.y) + (bb.x + bb.y) + (c.x + c.y) + (d.x + d.y);
        q = fmaf(a.x, a.x, q); q = fmaf(a.y, a.y, q);
        q = fmaf(bb.x, bb.x, q); q = fmaf(bb.y, bb.y, q);
        q = fmaf(c.x, c.x, q); q = fmaf(c.y, c.y, q);
        q = fmaf(d.x, d.x, q); q = fmaf(d.y, d.y, q);
    }
    __shared__ float ss[16], qq[16];
    const int wid = threadIdx.x >> 5, lane = threadIdx.x & 31;
#pragma unroll
    for (int off = 16; off; off >>= 1) {
        s += __shfl_xor_sync(0xffffffffu, s, off);
        q += __shfl_xor_sync(0xffffffffu, q, off);
    }
    if (lane == 0) { ss[wid] = s; qq[wid] = q; }
    __syncthreads();
    if (threadIdx.x == 0) {
        float S = 0.f, Q = 0.f;
#pragma unroll
        for (int i = 0; i < 16; i++) { S += ss[i]; Q += qq[i]; }
        if (b < 128) {
            float mean = S * invN;
            float var = Q * invN - mean * mean;
            float sc = rsqrtf(var + EPS);
            g_scale[b] = sc;
            g_bias[b] = -mean * sc;
        } else {
            // rms over group: Q summed over nrows rows; divide by N and l-dim
            float ms = Q * invN * ((nrows == 3) ? (1.f / 3.f) : 0.2f);
            float sc = rsqrtf(ms + EPS);
            for (int rr = 0; rr < nrows; rr++) {
                g_scale[row0 + rr] = sc;
                g_bias[row0 + rr] = 0.f;
            }
        }
    }
}

// ---------------- normalize + transpose to final layout (64-node tiles, fp16 in) ----------------
#define NORM_SMEM_BYTES (64 * 481 * 4)
__global__ void __launch_bounds__(512) k_norm(float* __restrict__ out) {
    extern __shared__ float ts[];   // [64][481]
    const int n0 = blockIdx.x * 64;
    const int tid = threadIdx.x;
    for (int idx = tid; idx < 480 * 8; idx += 512) {
        int f = idx >> 3, k = idx & 7;
        const uint2* src = (const uint2*)(g_outTh + (size_t)f * NN2 + n0 + 8 * k);
        uint2 raw = __ldcs(src);
        __half2 h0 = *(__half2*)&raw.x;
        __half2 h1 = *(__half2*)&raw.y;
        uint2 raw2 = __ldcs(src + 1);
        __half2 h2 = *(__half2*)&raw2.x;
        __half2 h3 = *(__half2*)&raw2.y;
        float2 f0 = __half22float2(h0), f1 = __half22float2(h1);
        float2 f2 = __half22float2(h2), f3 = __half22float2(h3);
        float sc = g_scale[f], bs = g_bias[f];
        float* tp = ts + (8 * k) * 481 + f;
        tp[0 * 481] = fmaf(f0.x, sc, bs);
        tp[1 * 481] = fmaf(f0.y, sc, bs);
        tp[2 * 481] = fmaf(f1.x, sc, bs);
        tp[3 * 481] = fmaf(f1.y, sc, bs);
        tp[4 * 481] = fmaf(f2.x, sc, bs);
        tp[5 * 481] = fmaf(f2.y, sc, bs);
        tp[6 * 481] = fmaf(f3.x, sc, bs);
        tp[7 * 481] = fmaf(f3.y, sc, bs);
    }
    __syncthreads();
    for (int idx = tid; idx < 64 * 120; idx += 512) {
        int n = idx / 120, q = idx - n * 120;
        if (n0 + n < NN) {
            float4 v = make_float4(ts[n * 481 + 4 * q],     ts[n * 481 + 4 * q + 1],
                                   ts[n * 481 + 4 * q + 2], ts[n * 481 + 4 * q + 3]);
            __stcs((float4*)(out + (size_t)(n0 + n) * 480 + 4 * q), v);
        }
    }
}

// ---------------- launch ----------------
extern "C" void kernel_launch(void* const* d_in, const int* in_sizes, int n_in,
                              void* d_out, int out_size) {
    const float* x   = (const float*)d_in[0];
    const float* pos = (const float*)d_in[1];
    const int*   ei  = (const int*)d_in[2];
    const float* tpw = (const float*)d_in[3];
    const float* W0a = (const float*)d_in[4];
    const float* W1a = (const float*)d_in[5];
    const float* W2a = (const float*)d_in[6];
    const float* W0b = (const float*)d_in[7];
    const float* W1b = (const float*)d_in[8];
    const float* W2b = (const float*)d_in[9];

    float* out  = (float*)d_out;
    float* erbf = out + (size_t)NN * 480;
    float* ersh = erbf + (size_t)NE * 16;

    cudaFuncSetAttribute(k_node, cudaFuncAttributeMaxDynamicSharedMemorySize, SMEM_BYTES);
    cudaFuncSetAttribute(k_norm, cudaFuncAttributeMaxDynamicSharedMemorySize, NORM_SMEM_BYTES);

    k_prep<<<(NN2 + 255) / 256, 256>>>(x, pos);
    k_edge<<<NE / 256, 256>>>(ei, erbf, ersh);
    k_node<<<148, 512, SMEM_BYTES>>>(tpw, W0a, W1a, W2a, W0b, W1b, W2b);
    k_stats<<<224, 512>>>();
    k_norm<<<NT64, 512, NORM_SMEM_BYTES>>>(out);
}

// round 17
// speedup vs baseline: 1.0295x; 1.0295x over previous
#include <cuda_runtime.h>
#include <cuda_fp16.h>
#include <math.h>
#include <stdint.h>

#define NN 100000
#define NN2 100032          // padded to multiple of 64
#define NE 3200000
#define NT64 1563           // ceil(NN / 64)

typedef unsigned long long ull;

// ---------------- device scratch ----------------
__device__ float g_a[NN2 * 12];        // segment sums, padded stride 12
__device__ float g_xp[NN * 12];        // [x0..x7][x8, py, pz, px]
__device__ __half g_outTh[480 * (size_t)NN2];  // fp16 transposed staging [feat][node]
__device__ float g_C112[45];
__device__ float g_W222[125];
__device__ float g_h0sum[128];
__device__ float g_h0sq[128];
__device__ float g_h1sq[192];
__device__ float g_h2sq[160];
__device__ __align__(16) float g_scale[480];
__device__ __align__(16) float g_bias[480];

__device__ __forceinline__ float fsigmoid(float x) {
    return __fdividef(1.f, 1.f + __expf(-x));
}
__device__ __forceinline__ ull pack2(float a, float b) {
    ull r; asm("mov.b64 %0, {%1,%2};" : "=l"(r) : "f"(a), "f"(b)); return r;
}
__device__ __forceinline__ void fma2(ull& d, ull a, ull b) {
    asm("fma.rn.f32x2 %0, %1, %2, %0;" : "+l"(d) : "l"(a), "l"(b));
}
__device__ __forceinline__ void unpack2(ull v, float& a, float& b) {
    asm("mov.b64 {%0,%1}, %2;" : "=f"(a), "=f"(b) : "l"(v));
}
__device__ __forceinline__ void st_h2_cs(__half* p, float a, float b) {
    __half2 h = __floats2half2_rn(a, b);
    unsigned int bits = *(unsigned int*)&h;
    asm volatile("st.global.cs.b32 [%0], %1;" :: "l"(p), "r"(bits) : "memory");
}

// ---------------- prep: pad x + pos fused, zero scratch, constants (block 0) ----------------
__global__ void k_prep(const float* __restrict__ x, const float* __restrict__ pos) {
    int n = blockIdx.x * blockDim.x + threadIdx.x;
    if (n < NN2) {
        float4 z = make_float4(0.f, 0.f, 0.f, 0.f);
        float4* ga = (float4*)(g_a + 12 * (size_t)n);
        ga[0] = z; ga[1] = z; ga[2] = z;
    }
    if (n < NN) {
        const float* xs = x + 9 * (size_t)n;
        float4* xp = (float4*)(g_xp + 12 * (size_t)n);
        xp[0] = make_float4(xs[0], xs[1], xs[2], xs[3]);
        xp[1] = make_float4(xs[4], xs[5], xs[6], xs[7]);
        xp[2] = make_float4(xs[8], pos[3 * n + 1], pos[3 * n + 2], pos[3 * n + 0]);
    }

    if (blockIdx.x == 0) {
        __shared__ float A[48];
        __shared__ float Ws[125];
        const int t = threadIdx.x;
        if (t < 45) A[t] = 0.f;
        __syncthreads();
        if (t == 0) {
            const float h = sqrtf(15.f) * 0.5f;
            const float s5 = sqrtf(5.f);
            A[0 * 9 + 0 * 3 + 2] = h; A[0 * 9 + 2 * 3 + 0] = h;
            A[1 * 9 + 0 * 3 + 1] = h; A[1 * 9 + 1 * 3 + 0] = h;
            A[2 * 9 + 0 * 3 + 0] = -0.5f * s5; A[2 * 9 + 1 * 3 + 1] = s5; A[2 * 9 + 2 * 3 + 2] = -0.5f * s5;
            A[3 * 9 + 1 * 3 + 2] = h; A[3 * 9 + 2 * 3 + 1] = h;
            A[4 * 9 + 0 * 3 + 0] = -h; A[4 * 9 + 2 * 3 + 2] = h;
        }
        __syncthreads();
        float ss = 0.f;
        for (int i = 0; i < 45; i++) ss += A[i] * A[i];
        float inv = 1.f / sqrtf(ss);
        if (t < 45) {
            int i = t / 15, j = (t % 15) / 5, m = t % 5;
            g_C112[t] = A[m * 9 + i * 3 + j] * inv;
        }
        if (t < 125) {
            int m = t / 25, nn = (t / 5) % 5, p = t % 5;
            float acc = 0.f, acc2 = 0.f;
            for (int i = 0; i < 3; i++)
                for (int k = 0; k < 3; k++)
                    for (int j = 0; j < 3; j++) {
                        acc  += A[m * 9 + i * 3 + k] * A[nn * 9 + k * 3 + j] * A[p * 9 + j * 3 + i];
                        acc2 += A[nn * 9 + i * 3 + k] * A[m * 9 + k * 3 + j] * A[p * 9 + j * 3 + i];
                    }
            Ws[t] = acc + acc2;
        }
        __syncthreads();
        if (t < 125) {
            float ss2 = 0.f;
            for (int i = 0; i < 125; i++) ss2 += Ws[i] * Ws[i];
            g_W222[t] = Ws[t] * (1.f / sqrtf(ss2));
        }
    }
}

// ---------------- edge kernel ----------------
__global__ void __launch_bounds__(256) k_edge(
    const int* __restrict__ ei,
    float* __restrict__ erbf, float* __restrict__ ersh)
{
    __shared__ float s_rbf[16 * 257];                 // [comp][edge], column-major
    __shared__ __align__(16) float s_sh9[256 * 9];    // [edge][comp], packed
    const int tid = threadIdx.x;
    const int e0 = blockIdx.x * 256;
    const int e = e0 + tid;

    int s = ei[e];
    int t = ei[NE + e];
    const float4* xps = (const float4*)(g_xp + 12 * (size_t)s);
    float4 xs2 = xps[2];
    float4 xt2 = ((const float4*)(g_xp + 12 * (size_t)t))[2];
    float vx = xt2.y - xs2.y, vy = xt2.z - xs2.z, vz = xt2.w - xs2.w;
    float r2 = vx * vx + vy * vy + vz * vz;
    float r = sqrtf(r2);
    float inv = __fdividef(1.f, fmaxf(r, 1e-12f));
    float ux = vx * inv, uy = vy * inv, uz = vz * inv;
    const float SQ3 = 1.7320508075688772f;
    const float SQ5 = 2.2360679774997896f;
    const float SQ15 = 3.8729833462074170f;
    float sh1 = SQ3 * ux, sh2 = SQ3 * uy, sh3 = SQ3 * uz;
    float sh4 = SQ15 * ux * uz;
    float sh5 = SQ15 * ux * uy;
    float sh6 = SQ5 * (uy * uy - 0.5f * (ux * ux + uz * uz));
    float sh7 = SQ15 * uy * uz;
    float sh8 = 0.5f * SQ15 * (uz * uz - ux * ux);
    float d = r * 0.1f;
    float d2 = d * d;
    float d5 = d2 * d2 * d;
    float fc = 1.f + d5 * (-21.f + d * (35.f - 15.f * d));
    fc = (d < 1.f) ? fc : 0.f;
    float ee = __expf(-d2) * fc;
    float g0 = ee, g1 = d * ee, g2 = d2 * ee;

    float4 xa = xps[0], xb = xps[1];
    float x8 = xs2.x;

    float* ga = g_a + 12 * (size_t)t;
    float m0 = xa.x * g0;
    float m1 = xa.y * sh1 * g1;
    float m2 = xa.z * sh2 * g1;
    float m3 = xa.w * sh3 * g1;
    float m4 = xb.x * sh4 * g2;
    float m5 = xb.y * sh5 * g2;
    float m6 = xb.z * sh6 * g2;
    float m7 = xb.w * sh7 * g2;
    float m8 = x8   * sh8 * g2;
    asm volatile("red.global.add.v4.f32 [%0], {%1,%2,%3,%4};"
                 :: "l"(ga), "f"(m0), "f"(m1), "f"(m2), "f"(m3) : "memory");
    asm volatile("red.global.add.v4.f32 [%0], {%1,%2,%3,%4};"
                 :: "l"(ga + 4), "f"(m4), "f"(m5), "f"(m6), "f"(m7) : "memory");
    atomicAdd(ga + 8, m8);

    float sp, cp;
    __sincosf(0.31415926535897931f * r, &sp, &cp);
    float coef = 0.44721359549995793f * inv * fc;
    float sprev = 0.f, scur = sp;
    float twoc = 2.f * cp;
#pragma unroll
    for (int n = 0; n < 16; n++) {
        s_rbf[n * 257 + tid] = coef * scur;
        float nx = twoc * scur - sprev;
        sprev = scur; scur = nx;
    }
    float* es = s_sh9 + tid * 9;
    es[0] = 1.f;
    es[1] = -sh1; es[2] = -sh2; es[3] = -sh3;
    es[4] = sh4; es[5] = sh5; es[6] = sh6; es[7] = sh7; es[8] = sh8;
    __syncthreads();

    float4* eb4 = (float4*)(erbf + (size_t)e0 * 16);
#pragma unroll
    for (int i = 0; i < 4; i++) {
        int k = tid + 256 * i;
        int eg = k >> 2, c0 = (k & 3) * 4;
        float4 v = make_float4(s_rbf[(c0 + 0) * 257 + eg], s_rbf[(c0 + 1) * 257 + eg],
                               s_rbf[(c0 + 2) * 257 + eg], s_rbf[(c0 + 3) * 257 + eg]);
        __stcs(&eb4[k], v);
    }
    float4* ep4 = (float4*)(ersh + (size_t)e0 * 9);
    const float4* ss4 = (const float4*)s_sh9;
    __stcs(&ep4[tid], ss4[tid]);
    __stcs(&ep4[tid + 256], ss4[tid + 256]);
    if (tid < 64) __stcs(&ep4[tid + 512], ss4[tid + 512]);
}

// ---------------- node kernel ----------------
#define SM_W0A   0        // 384
#define SM_W1A   384      // 256
#define SM_W2A   640      // 128
#define SM_W0B   768      // 16384 [k][f]
#define SM_W1B   17152    // 4096  [u][v]
#define SM_W2B   21248    // 1024  [u][v]
#define SM_TPW   22272    // 12
#define SM_C112  22284    // 48
#define SM_W222  22332    // 128
#define SM_S     22460    // 64*13 = 832
#define SM_OUTT  23292    // 35*64 = 2240
#define SM_H0    25532    // 128*64 = 8192
#define SM_H1    33724    // 192*64 = 12288
#define SM_H2    46012    // 160*64 = 10240
#define SMEM_FLOATS 56252
#define SMEM_BYTES (SMEM_FLOATS * 4)

template<int K, int WS, int AS>
__device__ __forceinline__ void taskB64(const float* __restrict__ ap,
                                        const ulonglong2* __restrict__ wp,
                                        __half* __restrict__ op, size_t rstride)
{
    ull A[8], B[8];
#pragma unroll
    for (int j = 0; j < 8; j++) { A[j] = 0; B[j] = 0; }
#pragma unroll 8
    for (int u = 0; u < K; u++) {
        ull av = *(const ull*)(ap + u * AS);
        float a0, a1; unpack2(av, a0, a1);
        ull p0 = pack2(a0, a0), p1 = pack2(a1, a1);
        ulonglong2 q0 = wp[u * WS],     q1 = wp[u * WS + 1];
        ulonglong2 q2 = wp[u * WS + 2], q3 = wp[u * WS + 3];
        fma2(A[0], p0, q0.x); fma2(B[0], p1, q0.x);
        fma2(A[1], p0, q0.y); fma2(B[1], p1, q0.y);
        fma2(A[2], p0, q1.x); fma2(B[2], p1, q1.x);
        fma2(A[3], p0, q1.y); fma2(B[3], p1, q1.y);
        fma2(A[4], p0, q2.x); fma2(B[4], p1, q2.x);
        fma2(A[5], p0, q2.y); fma2(B[5], p1, q2.y);
        fma2(A[6], p0, q3.x); fma2(B[6], p1, q3.x);
        fma2(A[7], p0, q3.y); fma2(B[7], p1, q3.y);
    }
#pragma unroll
    for (int j = 0; j < 8; j++) {
        float a0, a1, b0, b1;
        unpack2(A[j], a0, a1);
        unpack2(B[j], b0, b1);
        st_h2_cs(op + (size_t)(2 * j) * rstride,     a0, b0);
        st_h2_cs(op + (size_t)(2 * j + 1) * rstride, a1, b1);
    }
}

__global__ void __launch_bounds__(512) k_node(
    const float* __restrict__ tp_w,
    const float* __restrict__ W0a, const float* __restrict__ W1a, const float* __restrict__ W2a,
    const float* __restrict__ W0b, const float* __restrict__ W1b, const float* __restrict__ W2b)
{
    extern __shared__ float sm[];
    float* w0a  = sm + SM_W0A;
    float* w1a  = sm + SM_W1A;
    float* w2a  = sm + SM_W2A;
    float* w0b  = sm + SM_W0B;
    float* w1b  = sm + SM_W1B;
    float* w2b  = sm + SM_W2B;
    float* tpw  = sm + SM_TPW;
    float* c112 = sm + SM_C112;
    float* w222 = sm + SM_W222;
    float* s_sh = sm + SM_S;
    float* out_t = sm + SM_OUTT;
    float* h0aT = sm + SM_H0;
    float* h1aT = sm + SM_H1;
    float* h2aT = sm + SM_H2;

    const int tid = threadIdx.x;
    const int wid = tid >> 5;
    const int lane = tid & 31;

    for (int i = tid; i < 384; i += 512) w0a[i] = W0a[i];
    if (tid < 256) w1a[tid] = W1a[tid];
    if (tid >= 256 && tid < 384) w2a[tid - 256] = W2a[tid - 256];
    for (int i = tid; i < 16384; i += 512) w0b[i] = W0b[i];
    for (int i = tid; i < 4096;  i += 512) w1b[i] = W1b[i];
    for (int i = tid; i < 1024;  i += 512) w2b[i] = W2b[i];
    if (tid < 11)  tpw[tid]  = tp_w[tid];
    if (tid >= 32 && tid < 77)  c112[tid - 32] = g_C112[tid - 32];
    if (tid >= 128 && tid < 253) w222[tid - 128] = g_W222[tid - 128];
    __syncthreads();

    for (int tile = blockIdx.x; tile < NT64; tile += gridDim.x) {
        const int n0 = tile * 64;

        if (tid < 192) {
            int n = tid / 3;
            int c = tid - 3 * n;
            const float4* gp = (const float4*)(g_a + (size_t)(n0 + n) * 12);
            float4 v = gp[c];
            float* dst = s_sh + n * 13 + c * 4;
            dst[0] = v.x; dst[1] = v.y; dst[2] = v.z; dst[3] = v.w;
        }
        __syncthreads();

#pragma unroll
        for (int half = 0; half < 2; half++) {
            const int node = half * 32 + lane;
            float s[9];
#pragma unroll
            for (int i = 0; i < 9; i++) s[i] = s_sh[node * 13 + i];
#pragma unroll
            for (int kq = 0; kq < 3; kq++) {
                int q = wid + 16 * kq;
                if (q >= 35) continue;
                float val;
                if (q == 0) {
                    val = tpw[0] * s[0] * s[0];
                } else if (q == 1) {
                    float a = s[1] * s[1] + s[2] * s[2] + s[3] * s[3];
                    val = tpw[1] * a * 0.57735026918962573f;
                } else if (q == 2) {
                    float a = 0.f;
#pragma unroll
                    for (int m = 0; m < 5; m++) a = fmaf(s[4 + m], s[4 + m], a);
                    val = tpw[2] * a * 0.44721359549995793f;
                } else if (q < 6) {
                    val = tpw[3] * s[0] * s[1 + (q - 3)];
                } else if (q < 9) {
                    val = tpw[4] * s[1 + (q - 6)] * s[0];
                } else if (q < 12) {
                    int j = q - 9; float a = 0.f;
#pragma unroll
                    for (int i = 0; i < 3; i++)
#pragma unroll
                        for (int m = 0; m < 5; m++)
                            a = fmaf(c112[i * 15 + j * 5 + m], s[1 + i] * s[4 + m], a);
                    val = tpw[5] * a;
                } else if (q < 15) {
                    int i = q - 12; float a = 0.f;
#pragma unroll
                    for (int j = 0; j < 3; j++)
#pragma unroll
                        for (int m = 0; m < 5; m++)
                            a = fmaf(c112[i * 15 + j * 5 + m], s[1 + j] * s[4 + m], a);
                    val = tpw[6] * a;
                } else if (q < 20) {
                    val = tpw[7] * s[0] * s[4 + (q - 15)];
                } else if (q < 25) {
                    val = tpw[8] * s[4 + (q - 20)] * s[0];
                } else if (q < 30) {
                    int m = q - 25; float a = 0.f;
#pragma unroll
                    for (int i = 0; i < 3; i++)
#pragma unroll
                        for (int j = 0; j < 3; j++)
                            a = fmaf(c112[i * 15 + j * 5 + m], s[1 + i] * s[1 + j], a);
                    val = tpw[9] * a;
                } else {
                    int c = q - 30; float a = 0.f;
#pragma unroll
                    for (int aa = 0; aa < 5; aa++)
#pragma unroll
                        for (int bb = 0; bb < 5; bb++)
                            a = fmaf(w222[(aa * 5 + bb) * 5 + c], s[4 + aa] * s[4 + bb], a);
                    val = tpw[10] * a;
                }
                out_t[q * 64 + node] = val;
            }
        }
        __syncthreads();

#pragma unroll
        for (int half = 0; half < 2; half++) {
            const int node = half * 32 + lane;
            float o0 = out_t[node], o1 = out_t[64 + node], o2 = out_t[128 + node];
#pragma unroll
            for (int k = 0; k < 8; k++) {
                int f = wid + 16 * k;
                float hv = o0 * w0a[f] + o1 * w0a[128 + f] + o2 * w0a[256 + f];
                h0aT[f * 64 + node] = fsigmoid(hv);
            }
            float b1[12];
#pragma unroll
            for (int i = 0; i < 12; i++) b1[i] = out_t[(3 + i) * 64 + node];
#pragma unroll
            for (int k = 0; k < 4; k++) {
                int v = wid + 16 * k;
                float m0 = 0.f, m1 = 0.f, m2 = 0.f;
#pragma unroll
                for (int u = 0; u < 4; u++) {
                    float w = w1a[u * 64 + v];
                    m0 = fmaf(b1[u * 3 + 0], w, m0);
                    m1 = fmaf(b1[u * 3 + 1], w, m1);
                    m2 = fmaf(b1[u * 3 + 2], w, m2);
                }
                float gt = fsigmoid(sqrtf(m0 * m0 + m1 * m1 + m2 * m2));
                h1aT[(v * 3 + 0) * 64 + node] = m0 * gt;
                h1aT[(v * 3 + 1) * 64 + node] = m1 * gt;
                h1aT[(v * 3 + 2) * 64 + node] = m2 * gt;
            }
            float b2[20];
#pragma unroll
            for (int i = 0; i < 20; i++) b2[i] = out_t[(15 + i) * 64 + node];
#pragma unroll
            for (int k = 0; k < 2; k++) {
                int v = wid + 16 * k;
                float m[5] = {0.f, 0.f, 0.f, 0.f, 0.f};
#pragma unroll
                for (int u = 0; u < 4; u++) {
                    float w = w2a[u * 32 + v];
#pragma unroll
                    for (int mm = 0; mm < 5; mm++)
                        m[mm] = fmaf(b2[u * 5 + mm], w, m[mm]);
                }
                float nrm = m[0]*m[0] + m[1]*m[1] + m[2]*m[2] + m[3]*m[3] + m[4]*m[4];
                float gt = fsigmoid(sqrtf(nrm));
#pragma unroll
                for (int mm = 0; mm < 5; mm++) h2aT[(v * 5 + mm) * 64 + node] = m[mm] * gt;
            }
        }
        __syncthreads();

#pragma unroll
        for (int k8 = 0; k8 < 2; k8++) {
            const int t = wid + 16 * k8;
            if (t >= 30) continue;
            if (t < 8) {
                taskB64<128, 32, 64>(h0aT + 2 * lane,
                                     (const ulonglong2*)w0b + 4 * t,
                                     g_outTh + (size_t)(16 * t) * NN2 + n0 + 2 * lane,
                                     (size_t)NN2);
            } else if (t < 20) {
                const int idx = t - 8, m = idx >> 2, vg = idx & 3;
                taskB64<64, 16, 192>(h1aT + m * 64 + 2 * lane,
                                     (const ulonglong2*)w1b + 4 * vg,
                                     g_outTh + (size_t)(128 + 48 * vg + m) * NN2 + n0 + 2 * lane,
                                     (size_t)(3 * NN2));
            } else {
                const int idx = t - 20, m = idx >> 1, vg = idx & 1;
                taskB64<32, 8, 320>(h2aT + m * 64 + 2 * lane,
                                    (const ulonglong2*)w2b + 4 * vg,
                                    g_outTh + (size_t)(320 + 80 * vg + m) * NN2 + n0 + 2 * lane,
                                    (size_t)(5 * NN2));
            }
        }
        __syncthreads();
    }
}

// ---------------- stats over fp16 rows (real nodes only: no pad correction) ----------------
__global__ void __launch_bounds__(256) k_stats() {
    const int f = blockIdx.x;                 // 0..479
    const uint4* row = (const uint4*)(g_outTh + (size_t)f * NN2);
    float s = 0.f, q = 0.f;
    for (int i = threadIdx.x; i < NN / 8; i += 256) {   // 12500 uint4 = 100000 halves exactly
        uint4 raw = __ldcs(row + i);
        float2 a = __half22float2(*(__half2*)&raw.x);
        float2 b = __half22float2(*(__half2*)&raw.y);
        float2 c = __half22float2(*(__half2*)&raw.z);
        float2 d = __half22float2(*(__half2*)&raw.w);
        s += (a.x + a.y) + (b.x + b.y) + (c.x + c.y) + (d.x + d.y);
        q = fmaf(a.x, a.x, q); q = fmaf(a.y, a.y, q);
        q = fmaf(b.x, b.x, q); q = fmaf(b.y, b.y, q);
        q = fmaf(c.x, c.x, q); q = fmaf(c.y, c.y, q);
        q = fmaf(d.x, d.x, q); q = fmaf(d.y, d.y, q);
    }
    __shared__ float ss[8], qq[8];
    const int wid = threadIdx.x >> 5, lane = threadIdx.x & 31;
#pragma unroll
    for (int off = 16; off; off >>= 1) {
        s += __shfl_xor_sync(0xffffffffu, s, off);
        q += __shfl_xor_sync(0xffffffffu, q, off);
    }
    if (lane == 0) { ss[wid] = s; qq[wid] = q; }
    __syncthreads();
    if (threadIdx.x == 0) {
        float S = 0.f, Q = 0.f;
#pragma unroll
        for (int i = 0; i < 8; i++) { S += ss[i]; Q += qq[i]; }
        if (f < 128)      { g_h0sum[f] = S; g_h0sq[f] = Q; }
        else if (f < 320) { g_h1sq[f - 128] = Q; }
        else              { g_h2sq[f - 320] = Q; }
    }
}

// ---------------- scale/bias precompute ----------------
__global__ void k_scale() {
    int t = threadIdx.x;
    const float invN = 1.f / (float)NN;
    const float EPS = 1e-5f;
    if (t < 128) {
        float mean = g_h0sum[t] * invN;
        float var = g_h0sq[t] * invN - mean * mean;
        float sc = rsqrtf(var + EPS);
        g_scale[t] = sc;
        g_bias[t] = -mean * sc;
    } else if (t < 320) {
        int o = t - 128; int v = o / 3;
        float ms = (g_h1sq[3 * v] + g_h1sq[3 * v + 1] + g_h1sq[3 * v + 2]) * invN * (1.f / 3.f);
        g_scale[t] = rsqrtf(ms + EPS);
        g_bias[t] = 0.f;
    } else if (t < 480) {
        int o = t - 320; int v = o / 5;
        float ms = (g_h2sq[5 * v] + g_h2sq[5 * v + 1] + g_h2sq[5 * v + 2] +
                    g_h2sq[5 * v + 3] + g_h2sq[5 * v + 4]) * invN * 0.2f;
        g_scale[t] = rsqrtf(ms + EPS);
        g_bias[t] = 0.f;
    }
}

// ---------------- normalize + transpose to final layout (64-node tiles, fp16 in) ----------------
#define NORM_SMEM_BYTES (64 * 481 * 4)
__global__ void __launch_bounds__(512) k_norm(float* __restrict__ out) {
    extern __shared__ float ts[];   // [64][481]
    const int n0 = blockIdx.x * 64;
    const int tid = threadIdx.x;
    for (int idx = tid; idx < 480 * 8; idx += 512) {
        int f = idx >> 3, k = idx & 7;
        const uint2* src = (const uint2*)(g_outTh + (size_t)f * NN2 + n0 + 8 * k);
        uint2 raw = __ldcs(src);
        __half2 h0 = *(__half2*)&raw.x;
        __half2 h1 = *(__half2*)&raw.y;
        uint2 raw2 = __ldcs(src + 1);
        __half2 h2 = *(__half2*)&raw2.x;
        __half2 h3 = *(__half2*)&raw2.y;
        float2 f0 = __half22float2(h0), f1 = __half22float2(h1);
        float2 f2 = __half22float2(h2), f3 = __half22float2(h3);
        float sc = g_scale[f], bs = g_bias[f];
        float* tp = ts + (8 * k) * 481 + f;
        tp[0 * 481] = fmaf(f0.x, sc, bs);
        tp[1 * 481] = fmaf(f0.y, sc, bs);
        tp[2 * 481] = fmaf(f1.x, sc, bs);
        tp[3 * 481] = fmaf(f1.y, sc, bs);
        tp[4 * 481] = fmaf(f2.x, sc, bs);
        tp[5 * 481] = fmaf(f2.y, sc, bs);
        tp[6 * 481] = fmaf(f3.x, sc, bs);
        tp[7 * 481] = fmaf(f3.y, sc, bs);
    }
    __syncthreads();
    for (int idx = tid; idx < 64 * 120; idx += 512) {
        int n = idx / 120, q = idx - n * 120;
        if (n0 + n < NN) {
            float4 v = make_float4(ts[n * 481 + 4 * q],     ts[n * 481 + 4 * q + 1],
                                   ts[n * 481 + 4 * q + 2], ts[n * 481 + 4 * q + 3]);
            __stcs((float4*)(out + (size_t)(n0 + n) * 480 + 4 * q), v);
        }
    }
}

// ---------------- launch ----------------
extern "C" void kernel_launch(void* const* d_in, const int* in_sizes, int n_in,
                              void* d_out, int out_size) {
    const float* x   = (const float*)d_in[0];
    const float* pos = (const float*)d_in[1];
    const int*   ei  = (const int*)d_in[2];
    const float* tpw = (const float*)d_in[3];
    const float* W0a = (const float*)d_in[4];
    const float* W1a = (const float*)d_in[5];
    const float* W2a = (const float*)d_in[6];
    const float* W0b = (const float*)d_in[7];
    const float* W1b = (const float*)d_in[8];
    const float* W2b = (const float*)d_in[9];

    float* out  = (float*)d_out;
    float* erbf = out + (size_t)NN * 480;
    float* ersh = erbf + (size_t)NE * 16;

    cudaFuncSetAttribute(k_node, cudaFuncAttributeMaxDynamicSharedMemorySize, SMEM_BYTES);
    cudaFuncSetAttribute(k_norm, cudaFuncAttributeMaxDynamicSharedMemorySize, NORM_SMEM_BYTES);

    k_prep<<<(NN2 + 255) / 256, 256>>>(x, pos);
    k_edge<<<NE / 256, 256>>>(ei, erbf, ersh);
    k_node<<<148, 512, SMEM_BYTES>>>(tpw, W0a, W1a, W2a, W0b, W1b, W2b);
    k_stats<<<480, 256>>>();
    k_scale<<<1, 512>>>();
    k_norm<<<NT64, 512, NORM_SMEM_BYTES>>>(out);
}